// round 10
// baseline (speedup 1.0000x reference)
#include <cuda_runtime.h>
#include <cstdint>

// AtomDistances: B=16, A=4096, N=128
// out[b,a,n] = mask ? || pos[b,nbr[b,a,n]] - pos[b,a] + cell_offsets[b,a,n,:] @ cell[b] || : 0
//
// HBM-bound (~192 MB compulsory traffic -> ~24us floor at 8TB/s).
// One warp per atom; each lane handles 4 consecutive neighbors with fully
// vectorized coalesced loads (int4 indices, 3x float4 offsets, int4 mask,
// float4 store). Position gathers hit L1/L2 (48 KB per batch slice).
//
// Dtype facts established by fingerprinting previous failures:
//   neighbors: int32  (int64 read -> fused garbage indices -> illegal access)
//   mask:      int32  (uint8 read -> rel_err exactly sqrt(0.8) = 0.894)

#ifndef AD_B
#define AD_B 16
#define AD_A 4096
#define AD_N 128
#endif

__global__ void __launch_bounds__(256, 8)
atom_distances_kernel(const float* __restrict__ pos,   // (B, A, 3) f32
                      const int* __restrict__ nbr,     // (B, A, N) i32
                      const float* __restrict__ cell,  // (B, 3, 3) f32
                      const float* __restrict__ coff,  // (B, A, N, 3) f32
                      const int* __restrict__ mask,    // (B, A, N) i32 (0/1)
                      float* __restrict__ out)         // (B, A, N) f32
{
    // global warp id == atom id (b*A + a)
    const int warp_global = (blockIdx.x * blockDim.x + threadIdx.x) >> 5;
    const int lane = threadIdx.x & 31;
    if (warp_global >= AD_B * AD_A) return;

    const int b = warp_global >> 12;          // / 4096
    const float* __restrict__ posb = pos + (size_t)b * AD_A * 3;

    // this lane's 4 neighbors: linear element index base
    const size_t base = (size_t)warp_global * AD_N + (size_t)lane * 4;

    // ---- kick off all streaming loads first (max MLP) ----
    const int4 nb4 = *reinterpret_cast<const int4*>(nbr + base);

    const float4* cof4 = reinterpret_cast<const float4*>(coff + base * 3);
    const float4 o0 = __ldg(cof4 + 0);
    const float4 o1 = __ldg(cof4 + 1);
    const float4 o2 = __ldg(cof4 + 2);

    const int4 m4 = *reinterpret_cast<const int4*>(mask + base);

    // center position (warp-uniform broadcast, L1)
    const float* pc = pos + (size_t)warp_global * 3;
    const float cx = __ldg(pc + 0);
    const float cy = __ldg(pc + 1);
    const float cz = __ldg(pc + 2);

    // cell matrix (row-major 3x3), warp-uniform
    const float* cm = cell + b * 9;
    const float c00 = __ldg(cm + 0), c01 = __ldg(cm + 1), c02 = __ldg(cm + 2);
    const float c10 = __ldg(cm + 3), c11 = __ldg(cm + 4), c12 = __ldg(cm + 5);
    const float c20 = __ldg(cm + 6), c21 = __ldg(cm + 7), c22 = __ldg(cm + 8);

    // gather neighbor positions (L1/L2-resident: 48KB per batch)
    const int js[4] = {nb4.x, nb4.y, nb4.z, nb4.w};
    float px[4], py[4], pz[4];
#pragma unroll
    for (int i = 0; i < 4; ++i) {
        const float* pj = posb + (size_t)js[i] * 3;
        px[i] = __ldg(pj + 0);
        py[i] = __ldg(pj + 1);
        pz[i] = __ldg(pj + 2);
    }

    // de-interleave AoS xyz offsets for the 4 neighbors
    const float ox[4] = {o0.x, o0.w, o1.z, o2.y};
    const float oy[4] = {o0.y, o1.x, o1.w, o2.z};
    const float oz[4] = {o0.z, o1.y, o2.x, o2.w};
    const int   ks[4] = {m4.x, m4.y, m4.z, m4.w};

    float4 res;
    float* r = reinterpret_cast<float*>(&res);
#pragma unroll
    for (int i = 0; i < 4; ++i) {
        // offsets @ cell : e-component = sum_d co[d] * cell[d][e]
        const float tx = ox[i] * c00 + oy[i] * c10 + oz[i] * c20;
        const float ty = ox[i] * c01 + oy[i] * c11 + oz[i] * c21;
        const float tz = ox[i] * c02 + oy[i] * c12 + oz[i] * c22;
        const float dx = px[i] - cx + tx;
        const float dy = py[i] - cy + ty;
        const float dz = pz[i] - cz + tz;
        const float d  = sqrtf(dx * dx + dy * dy + dz * dz);
        r[i] = (ks[i] != 0) ? d : 0.0f;
    }

    *reinterpret_cast<float4*>(out + base) = res;
}

extern "C" void kernel_launch(void* const* d_in, const int* in_sizes, int n_in,
                              void* d_out, int out_size) {
    const float* positions = (const float*)d_in[0];
    const int*   neighbors = (const int*)d_in[1];
    const float* cell      = (const float*)d_in[2];
    const float* cell_off  = (const float*)d_in[3];
    const int*   mask      = (const int*)d_in[4];
    float*       out       = (float*)d_out;

    // one warp per atom: B*A = 65536 warps; 8 warps/block -> 8192 blocks
    const int total_warps = AD_B * AD_A;
    const int threads = 256;
    const int blocks = (total_warps * 32 + threads - 1) / threads;
    atom_distances_kernel<<<blocks, threads>>>(positions, neighbors, cell,
                                               cell_off, mask, out);
}

// round 11
// speedup vs baseline: 1.0043x; 1.0043x over previous
#include <cuda_runtime.h>
#include <cstdint>

// AtomDistances: B=16, A=4096, N=128
// out[b,a,n] = mask ? || pos[b,nbr[b,a,n]] - pos[b,a] + cell_offsets[b,a,n,:] @ cell[b] || : 0
//
// HBM-bound (~192 MB compulsory traffic -> ~24us floor at 8TB/s).
// One warp per atom; each lane handles 4 consecutive neighbors with fully
// vectorized coalesced loads (int4 indices, 3x float4 offsets, int4 mask,
// float4 store). Position gathers hit L1/L2 (48 KB per batch slice).
//
// Dtype facts established by fingerprinting previous failures:
//   neighbors: int32  (int64 read -> fused garbage indices -> illegal access)
//   mask:      int32  (uint8 read -> rel_err exactly sqrt(0.8) = 0.894)

#ifndef AD_B
#define AD_B 16
#define AD_A 4096
#define AD_N 128
#endif

__global__ void __launch_bounds__(256, 8)
atom_distances_kernel(const float* __restrict__ pos,   // (B, A, 3) f32
                      const int* __restrict__ nbr,     // (B, A, N) i32
                      const float* __restrict__ cell,  // (B, 3, 3) f32
                      const float* __restrict__ coff,  // (B, A, N, 3) f32
                      const int* __restrict__ mask,    // (B, A, N) i32 (0/1)
                      float* __restrict__ out)         // (B, A, N) f32
{
    // global warp id == atom id (b*A + a)
    const int warp_global = (blockIdx.x * blockDim.x + threadIdx.x) >> 5;
    const int lane = threadIdx.x & 31;
    if (warp_global >= AD_B * AD_A) return;

    const int b = warp_global >> 12;          // / 4096
    const float* __restrict__ posb = pos + (size_t)b * AD_A * 3;

    // this lane's 4 neighbors: linear element index base
    const size_t base = (size_t)warp_global * AD_N + (size_t)lane * 4;

    // ---- kick off all streaming loads first (max MLP) ----
    const int4 nb4 = *reinterpret_cast<const int4*>(nbr + base);

    const float4* cof4 = reinterpret_cast<const float4*>(coff + base * 3);
    const float4 o0 = __ldg(cof4 + 0);
    const float4 o1 = __ldg(cof4 + 1);
    const float4 o2 = __ldg(cof4 + 2);

    const int4 m4 = *reinterpret_cast<const int4*>(mask + base);

    // center position (warp-uniform broadcast, L1)
    const float* pc = pos + (size_t)warp_global * 3;
    const float cx = __ldg(pc + 0);
    const float cy = __ldg(pc + 1);
    const float cz = __ldg(pc + 2);

    // cell matrix (row-major 3x3), warp-uniform
    const float* cm = cell + b * 9;
    const float c00 = __ldg(cm + 0), c01 = __ldg(cm + 1), c02 = __ldg(cm + 2);
    const float c10 = __ldg(cm + 3), c11 = __ldg(cm + 4), c12 = __ldg(cm + 5);
    const float c20 = __ldg(cm + 6), c21 = __ldg(cm + 7), c22 = __ldg(cm + 8);

    // gather neighbor positions (L1/L2-resident: 48KB per batch)
    const int js[4] = {nb4.x, nb4.y, nb4.z, nb4.w};
    float px[4], py[4], pz[4];
#pragma unroll
    for (int i = 0; i < 4; ++i) {
        const float* pj = posb + (size_t)js[i] * 3;
        px[i] = __ldg(pj + 0);
        py[i] = __ldg(pj + 1);
        pz[i] = __ldg(pj + 2);
    }

    // de-interleave AoS xyz offsets for the 4 neighbors
    const float ox[4] = {o0.x, o0.w, o1.z, o2.y};
    const float oy[4] = {o0.y, o1.x, o1.w, o2.z};
    const float oz[4] = {o0.z, o1.y, o2.x, o2.w};
    const int   ks[4] = {m4.x, m4.y, m4.z, m4.w};

    float4 res;
    float* r = reinterpret_cast<float*>(&res);
#pragma unroll
    for (int i = 0; i < 4; ++i) {
        // offsets @ cell : e-component = sum_d co[d] * cell[d][e]
        const float tx = ox[i] * c00 + oy[i] * c10 + oz[i] * c20;
        const float ty = ox[i] * c01 + oy[i] * c11 + oz[i] * c21;
        const float tz = ox[i] * c02 + oy[i] * c12 + oz[i] * c22;
        const float dx = px[i] - cx + tx;
        const float dy = py[i] - cy + ty;
        const float dz = pz[i] - cz + tz;
        const float d  = sqrtf(dx * dx + dy * dy + dz * dz);
        r[i] = (ks[i] != 0) ? d : 0.0f;
    }

    *reinterpret_cast<float4*>(out + base) = res;
}

extern "C" void kernel_launch(void* const* d_in, const int* in_sizes, int n_in,
                              void* d_out, int out_size) {
    const float* positions = (const float*)d_in[0];
    const int*   neighbors = (const int*)d_in[1];
    const float* cell      = (const float*)d_in[2];
    const float* cell_off  = (const float*)d_in[3];
    const int*   mask      = (const int*)d_in[4];
    float*       out       = (float*)d_out;

    // one warp per atom: B*A = 65536 warps; 8 warps/block -> 8192 blocks
    const int total_warps = AD_B * AD_A;
    const int threads = 256;
    const int blocks = (total_warps * 32 + threads - 1) / threads;
    atom_distances_kernel<<<blocks, threads>>>(positions, neighbors, cell,
                                               cell_off, mask, out);
}

// round 12
// speedup vs baseline: 1.5161x; 1.5097x over previous
#include <cuda_runtime.h>
#include <cstdint>

// AtomDistances: B=16, A=4096, N=128
// out[b,a,n] = mask ? || pos[b,nbr[b,a,n]] - pos[b,a] + cell_offsets[b,a,n,:] @ cell[b] || : 0
//
// R11 profile: L1tex 66% (binding), DRAM 40%. The 12 random scalar position
// gathers per thread generated ~10x the L1tex wavefronts of all streaming
// loads combined. Fix: stage the 48KB per-batch position slice in shared
// memory once per block and gather via LDS (smem crossbar), with each block
// covering 32 atoms so staging traffic == gather traffic (1:1 amortization).
//
// Dtypes (established by failure fingerprinting): neighbors=int32, mask=int32.

#ifndef AD_B
#define AD_B 16
#define AD_A 4096
#define AD_N 128
#endif

#define ATOMS_PER_BLOCK 32
#define THREADS 256
#define SMEM_FLOATS (AD_A * 3)            // 12288 floats = 48 KB

__global__ void __launch_bounds__(THREADS, 4)
atom_distances_kernel(const float* __restrict__ pos,   // (B, A, 3) f32
                      const int* __restrict__ nbr,     // (B, A, N) i32
                      const float* __restrict__ cell,  // (B, 3, 3) f32
                      const float* __restrict__ coff,  // (B, A, N, 3) f32
                      const int* __restrict__ mask,    // (B, A, N) i32 (0/1)
                      float* __restrict__ out)         // (B, A, N) f32
{
    extern __shared__ float spos[];       // staged positions, 48 KB

    const int tid  = threadIdx.x;
    const int lane = tid & 31;
    const int warp = tid >> 5;            // 0..7

    // block -> (batch, atom group of 32)
    const int groups_per_batch = AD_A / ATOMS_PER_BLOCK;        // 128
    const int b = blockIdx.x / groups_per_batch;
    const int g = blockIdx.x % groups_per_batch;

    // ---- stage this batch's positions into smem (coalesced float4 copy) ----
    {
        const float4* __restrict__ src = reinterpret_cast<const float4*>(
            pos + (size_t)b * SMEM_FLOATS);
        float4* dst = reinterpret_cast<float4*>(spos);
#pragma unroll
        for (int i = 0; i < SMEM_FLOATS / 4 / THREADS; ++i)     // 12 iters
            dst[tid + i * THREADS] = src[tid + i * THREADS];
    }

    // cell matrix (row-major 3x3), warp-uniform, L1-resident
    const float* cm = cell + b * 9;
    const float c00 = __ldg(cm + 0), c01 = __ldg(cm + 1), c02 = __ldg(cm + 2);
    const float c10 = __ldg(cm + 3), c11 = __ldg(cm + 4), c12 = __ldg(cm + 5);
    const float c20 = __ldg(cm + 6), c21 = __ldg(cm + 7), c22 = __ldg(cm + 8);

    __syncthreads();

    // ---- each warp handles 4 atoms; each lane 4 consecutive neighbors ----
#pragma unroll
    for (int it = 0; it < ATOMS_PER_BLOCK / 8; ++it) {          // 4 iters
        const int a_in_batch = g * ATOMS_PER_BLOCK + warp * 4 + it;
        const size_t base = ((size_t)b * AD_A + a_in_batch) * (size_t)AD_N
                          + (size_t)lane * 4;

        // streaming loads (coalesced, vectorized)
        const int4 nb4 = *reinterpret_cast<const int4*>(nbr + base);
        const float4* cof4 = reinterpret_cast<const float4*>(coff + base * 3);
        const float4 o0 = __ldg(cof4 + 0);
        const float4 o1 = __ldg(cof4 + 1);
        const float4 o2 = __ldg(cof4 + 2);
        const int4 m4 = *reinterpret_cast<const int4*>(mask + base);

        // center position from smem (broadcast)
        const float cx = spos[a_in_batch * 3 + 0];
        const float cy = spos[a_in_batch * 3 + 1];
        const float cz = spos[a_in_batch * 3 + 2];

        // gather neighbor positions from smem crossbar
        const int js[4] = {nb4.x, nb4.y, nb4.z, nb4.w};
        float px[4], py[4], pz[4];
#pragma unroll
        for (int i = 0; i < 4; ++i) {
            const int o = js[i] * 3;
            px[i] = spos[o + 0];
            py[i] = spos[o + 1];
            pz[i] = spos[o + 2];
        }

        // de-interleave AoS xyz offsets for the 4 neighbors
        const float ox[4] = {o0.x, o0.w, o1.z, o2.y};
        const float oy[4] = {o0.y, o1.x, o1.w, o2.z};
        const float oz[4] = {o0.z, o1.y, o2.x, o2.w};
        const int   ks[4] = {m4.x, m4.y, m4.z, m4.w};

        float4 res;
        float* r = reinterpret_cast<float*>(&res);
#pragma unroll
        for (int i = 0; i < 4; ++i) {
            // offsets @ cell : e = sum_d co[d] * cell[d][e]
            const float tx = ox[i] * c00 + oy[i] * c10 + oz[i] * c20;
            const float ty = ox[i] * c01 + oy[i] * c11 + oz[i] * c21;
            const float tz = ox[i] * c02 + oy[i] * c12 + oz[i] * c22;
            const float dx = px[i] - cx + tx;
            const float dy = py[i] - cy + ty;
            const float dz = pz[i] - cz + tz;
            const float d  = sqrtf(dx * dx + dy * dy + dz * dz);
            r[i] = (ks[i] != 0) ? d : 0.0f;
        }

        *reinterpret_cast<float4*>(out + base) = res;
    }
}

extern "C" void kernel_launch(void* const* d_in, const int* in_sizes, int n_in,
                              void* d_out, int out_size) {
    const float* positions = (const float*)d_in[0];
    const int*   neighbors = (const int*)d_in[1];
    const float* cell      = (const float*)d_in[2];
    const float* cell_off  = (const float*)d_in[3];
    const int*   mask      = (const int*)d_in[4];
    float*       out       = (float*)d_out;

    const int blocks = AD_B * (AD_A / ATOMS_PER_BLOCK);   // 2048
    const size_t smem = SMEM_FLOATS * sizeof(float);      // 49152 B
    atom_distances_kernel<<<blocks, THREADS, smem>>>(positions, neighbors, cell,
                                                     cell_off, mask, out);
}

// round 13
// speedup vs baseline: 1.5260x; 1.0065x over previous
#include <cuda_runtime.h>
#include <cstdint>

// AtomDistances: B=16, A=4096, N=128
// out[b,a,n] = mask ? || pos[b,nbr[b,a,n]] - pos[b,a] + cell_offsets[b,a,n,:] @ cell[b] || : 0
//
// R12: 39.7us, DRAM 65.7%, L1 66%, occ 44%. DRAM floor ~28us (192MB compulsory).
// R13 changes: 512 threads/block, 64 atoms/block ->
//   - staging traffic halves (96MB -> 48MB L2-resident; 12 -> 6 wf/atom)
//   - occupancy 32 -> 48 warps/SM via __launch_bounds__(512,3) (regs ~42)
//   - per-neighbor compute fused with its gather to keep live regs under cap
//
// Dtypes (established by failure fingerprinting): neighbors=int32, mask=int32.

#ifndef AD_B
#define AD_B 16
#define AD_A 4096
#define AD_N 128
#endif

#define ATOMS_PER_BLOCK 64
#define THREADS 512
#define SMEM_FLOATS (AD_A * 3)            // 12288 floats = 48 KB

__global__ void __launch_bounds__(THREADS, 3)
atom_distances_kernel(const float* __restrict__ pos,   // (B, A, 3) f32
                      const int* __restrict__ nbr,     // (B, A, N) i32
                      const float* __restrict__ cell,  // (B, 3, 3) f32
                      const float* __restrict__ coff,  // (B, A, N, 3) f32
                      const int* __restrict__ mask,    // (B, A, N) i32 (0/1)
                      float* __restrict__ out)         // (B, A, N) f32
{
    extern __shared__ float spos[];       // staged positions, 48 KB

    const int tid  = threadIdx.x;
    const int lane = tid & 31;
    const int warp = tid >> 5;            // 0..15

    // block -> (batch, atom group of 64)
    const int groups_per_batch = AD_A / ATOMS_PER_BLOCK;        // 64
    const int b = blockIdx.x / groups_per_batch;
    const int g = blockIdx.x % groups_per_batch;

    // ---- stage this batch's positions into smem (coalesced float4 copy) ----
    {
        const float4* __restrict__ src = reinterpret_cast<const float4*>(
            pos + (size_t)b * SMEM_FLOATS);
        float4* dst = reinterpret_cast<float4*>(spos);
#pragma unroll
        for (int i = 0; i < SMEM_FLOATS / 4 / THREADS; ++i)     // 6 iters
            dst[tid + i * THREADS] = src[tid + i * THREADS];
    }

    // cell matrix (row-major 3x3), warp-uniform, L1-resident
    const float* cm = cell + b * 9;
    const float c00 = __ldg(cm + 0), c01 = __ldg(cm + 1), c02 = __ldg(cm + 2);
    const float c10 = __ldg(cm + 3), c11 = __ldg(cm + 4), c12 = __ldg(cm + 5);
    const float c20 = __ldg(cm + 6), c21 = __ldg(cm + 7), c22 = __ldg(cm + 8);

    __syncthreads();

    // ---- each warp handles 4 atoms; each lane 4 consecutive neighbors ----
#pragma unroll
    for (int it = 0; it < ATOMS_PER_BLOCK / 16; ++it) {         // 4 iters
        const int a_in_batch = g * ATOMS_PER_BLOCK + warp * 4 + it;
        const size_t base = ((size_t)b * AD_A + a_in_batch) * (size_t)AD_N
                          + (size_t)lane * 4;

        // streaming loads (coalesced, vectorized) — issue all upfront
        const int4 nb4 = *reinterpret_cast<const int4*>(nbr + base);
        const float4* cof4 = reinterpret_cast<const float4*>(coff + base * 3);
        const float4 o0 = __ldg(cof4 + 0);
        const float4 o1 = __ldg(cof4 + 1);
        const float4 o2 = __ldg(cof4 + 2);
        const int4 m4 = *reinterpret_cast<const int4*>(mask + base);

        // center position from smem (broadcast)
        const float cx = spos[a_in_batch * 3 + 0];
        const float cy = spos[a_in_batch * 3 + 1];
        const float cz = spos[a_in_batch * 3 + 2];

        float4 res;

        // per-neighbor: gather from smem crossbar, compute immediately
        // (keeps live register set small; LDS latency 29cyc hidden by TLP)
        {
            const int o = nb4.x * 3;
            const float tx = o0.x * c00 + o0.y * c10 + o0.z * c20;
            const float ty = o0.x * c01 + o0.y * c11 + o0.z * c21;
            const float tz = o0.x * c02 + o0.y * c12 + o0.z * c22;
            const float dx = spos[o + 0] - cx + tx;
            const float dy = spos[o + 1] - cy + ty;
            const float dz = spos[o + 2] - cz + tz;
            res.x = (m4.x != 0) ? sqrtf(dx*dx + dy*dy + dz*dz) : 0.0f;
        }
        {
            const int o = nb4.y * 3;
            const float tx = o0.w * c00 + o1.x * c10 + o1.y * c20;
            const float ty = o0.w * c01 + o1.x * c11 + o1.y * c21;
            const float tz = o0.w * c02 + o1.x * c12 + o1.y * c22;
            const float dx = spos[o + 0] - cx + tx;
            const float dy = spos[o + 1] - cy + ty;
            const float dz = spos[o + 2] - cz + tz;
            res.y = (m4.y != 0) ? sqrtf(dx*dx + dy*dy + dz*dz) : 0.0f;
        }
        {
            const int o = nb4.z * 3;
            const float tx = o1.z * c00 + o1.w * c10 + o2.x * c20;
            const float ty = o1.z * c01 + o1.w * c11 + o2.x * c21;
            const float tz = o1.z * c02 + o1.w * c12 + o2.x * c22;
            const float dx = spos[o + 0] - cx + tx;
            const float dy = spos[o + 1] - cy + ty;
            const float dz = spos[o + 2] - cz + tz;
            res.z = (m4.z != 0) ? sqrtf(dx*dx + dy*dy + dz*dz) : 0.0f;
        }
        {
            const int o = nb4.w * 3;
            const float tx = o2.y * c00 + o2.z * c10 + o2.w * c20;
            const float ty = o2.y * c01 + o2.z * c11 + o2.w * c21;
            const float tz = o2.y * c02 + o2.z * c12 + o2.w * c22;
            const float dx = spos[o + 0] - cx + tx;
            const float dy = spos[o + 1] - cy + ty;
            const float dz = spos[o + 2] - cz + tz;
            res.w = (m4.w != 0) ? sqrtf(dx*dx + dy*dy + dz*dz) : 0.0f;
        }

        *reinterpret_cast<float4*>(out + base) = res;
    }
}

extern "C" void kernel_launch(void* const* d_in, const int* in_sizes, int n_in,
                              void* d_out, int out_size) {
    const float* positions = (const float*)d_in[0];
    const int*   neighbors = (const int*)d_in[1];
    const float* cell      = (const float*)d_in[2];
    const float* cell_off  = (const float*)d_in[3];
    const int*   mask      = (const int*)d_in[4];
    float*       out       = (float*)d_out;

    const int blocks = AD_B * (AD_A / ATOMS_PER_BLOCK);   // 1024
    const size_t smem = SMEM_FLOATS * sizeof(float);      // 49152 B
    atom_distances_kernel<<<blocks, THREADS, smem>>>(positions, neighbors, cell,
                                                     cell_off, mask, out);
}